// round 14
// baseline (speedup 1.0000x reference)
#include <cuda_runtime.h>
#include <cuda_bf16.h>
#include <cstdint>
#include <cstddef>

// ---------------------------------------------------------------------------
// AWD-LSTM forward: embed -> DeFINE -> 3x LSTM -> tied-embedding logits
// Shapes: B=32, T=128, V=32000, E=400, M=512, H=1152.
// Round 14: recurrence reverted to proven fp32 FFMA2 lstm_step (R10);
// ALL five parallel GEMMs now on legacy tensor cores via one generic
// gemm_hmma (3-term bf16 hi/lo split, validated in R12/R13). DeFINE and
// the lstm epilogues emit pre-split bf16 operands for the next GEMM.
// ---------------------------------------------------------------------------

#define Bb 32
#define Tt 128
#define Vv 32000
#define Ee 400
#define Mm 512
#define Hh 1152
#define NT 4096           // B*T tokens
#define EKP 448           // emb K padded (400 -> 448)

// ---- scratch (device globals; no allocation allowed) ----
__device__ float g_PRE[NT * 4608];                  // gate preacts (has bih)
__device__ float g_HT [2][Hh * 32];                 // h ping-pong [d][32] fp32
__device__ float g_CT [Hh * 32];                    // c [d][32] fp32
__device__ __nv_bfloat16 g_E0[(size_t)Vv * EKP];    // emb hi
__device__ __nv_bfloat16 g_E1[(size_t)Vv * EKP];    // emb lo
__device__ __nv_bfloat16 g_WT0[512 * EKP];          // define_W^T hi
__device__ __nv_bfloat16 g_WT1[512 * EKP];          // define_W^T lo
__device__ __nv_bfloat16 g_WB0[(size_t)4608 * Hh];  // Wih splits (per layer)
__device__ __nv_bfloat16 g_WB1[(size_t)4608 * Hh];
__device__ __nv_bfloat16 g_AB0[(size_t)NT * Hh];    // activation splits
__device__ __nv_bfloat16 g_AB1[(size_t)NT * Hh];
__device__ __nv_bfloat16 g_A0[(size_t)NT * EKP];    // Y2 split (pad stays 0)
__device__ __nv_bfloat16 g_A1[(size_t)NT * EKP];

// ---- packed fp32 helpers ----
__device__ __forceinline__ unsigned long long ffma2(
    unsigned long long a, unsigned long long b, unsigned long long c)
{
    unsigned long long d;
    asm("fma.rn.f32x2 %0, %1, %2, %3;" : "=l"(d) : "l"(a), "l"(b), "l"(c));
    return d;
}
__device__ __forceinline__ unsigned long long pack2(float lo, float hi)
{
    unsigned long long r;
    asm("mov.b64 %0, {%1, %2};" : "=l"(r) : "f"(lo), "f"(hi));
    return r;
}
__device__ __forceinline__ float2 unpack2(unsigned long long v)
{
    float lo, hi;
    asm("mov.b64 {%0, %1}, %2;" : "=f"(lo), "=f"(hi) : "l"(v));
    return make_float2(lo, hi);
}
union F4U { float4 f; unsigned long long u[2]; };

__device__ __forceinline__ void hmma16816(
    float& c0, float& c1, float& c2, float& c3,
    uint32_t a0, uint32_t a1, uint32_t a2, uint32_t a3,
    uint32_t b0, uint32_t b1)
{
    asm volatile(
        "mma.sync.aligned.m16n8k16.row.col.f32.bf16.bf16.f32 "
        "{%0,%1,%2,%3}, {%4,%5,%6,%7}, {%8,%9}, {%0,%1,%2,%3};"
        : "+f"(c0), "+f"(c1), "+f"(c2), "+f"(c3)
        : "r"(a0), "r"(a1), "r"(a2), "r"(a3), "r"(b0), "r"(b1));
}

// ---------------------------------------------------------------------------
// Generic HMMA GEMM-NT:  C[M,N] = A[M,Kp] @ B[N,Kp]^T + bias[N]
// A,B pre-split bf16 (hi/lo); 3-term product a0b0 + a0b1 + a1b0.
// CTA 128x128, 8 warps (64x32 warp tile), K chunks of 32, smem rows padded
// to 40 bf16 (conflict-free fragment loads). Optional ids row-gather on A,
// optional N tail (guarded B-rows/stores), optional bf16-split output.
// Structure identical to the R12-validated logits kernel.
// ---------------------------------------------------------------------------
#define LDP 40
#define LG_TILE (128 * LDP * 2)
#define LG_SMEM (4 * LG_TILE)

__global__ __launch_bounds__(256, 2) void gemm_hmma(
    const __nv_bfloat16* __restrict__ A0, const __nv_bfloat16* __restrict__ A1,
    const __nv_bfloat16* __restrict__ B0, const __nv_bfloat16* __restrict__ B1,
    float* __restrict__ C, const float* __restrict__ bias,
    const int* __restrict__ ids,
    __nv_bfloat16* __restrict__ S0, __nv_bfloat16* __restrict__ S1,
    int N, int Kp, size_t ldc, int kso)
{
    extern __shared__ char smc[];

    const int tid  = threadIdx.x;
    const int wid  = tid >> 5;
    const int lane = tid & 31;
    const int wm   = wid & 1;
    const int wn   = wid >> 1;

    const int n0 = blockIdx.x * 128;
    const int m0 = blockIdx.y * 128;

    // staging: 64 threads per matrix, 2 rows per thread
    const int mtx = tid >> 6;
    const int rp  = tid & 63;
    const __nv_bfloat16 *s0, *s1;
    if (mtx < 2) {
        const int mr0 = m0 + 2 * rp, mr1 = m0 + 2 * rp + 1;
        const int ar0 = ids ? ids[mr0] : mr0;
        const int ar1 = ids ? ids[mr1] : mr1;
        const __nv_bfloat16* base = (mtx == 0) ? A0 : A1;
        s0 = base + (size_t)ar0 * Kp;
        s1 = base + (size_t)ar1 * Kp;
    } else {
        const int nr0 = n0 + 2 * rp, nr1 = n0 + 2 * rp + 1;
        const __nv_bfloat16* base = (mtx == 2) ? B0 : B1;
        s0 = base + (size_t)(nr0 < N ? nr0 : 0) * Kp;
        s1 = base + (size_t)(nr1 < N ? nr1 : 0) * Kp;
    }
    char* dst0 = smc + mtx * LG_TILE + (2 * rp    ) * (LDP * 2);
    char* dst1 = smc + mtx * LG_TILE + (2 * rp + 1) * (LDP * 2);

    float acc[4][4][4];
    #pragma unroll
    for (int i = 0; i < 4; ++i)
        #pragma unroll
        for (int j = 0; j < 4; ++j)
            #pragma unroll
            for (int k = 0; k < 4; ++k) acc[i][j][k] = 0.f;

    const char* asm0 = smc;
    const char* asm1 = smc + LG_TILE;
    const char* bsm0 = smc + 2 * LG_TILE;
    const char* bsm1 = smc + 3 * LG_TILE;

    const int arow = (lane >> 2);
    const int akof = (lane & 3) * 2;

    const int nchunk = Kp >> 5;
    for (int c = 0; c < nchunk; ++c) {
        __syncthreads();
        {
            const char* p0 = (const char*)(s0 + c * 32);
            const char* p1 = (const char*)(s1 + c * 32);
            #pragma unroll
            for (int i = 0; i < 4; ++i) {
                *(uint4*)(dst0 + i * 16) = *(const uint4*)(p0 + i * 16);
                *(uint4*)(dst1 + i * 16) = *(const uint4*)(p1 + i * 16);
            }
        }
        __syncthreads();

        #pragma unroll
        for (int ks = 0; ks < 2; ++ks) {
            const int kbyte = (ks * 16 + akof) * 2;

            uint32_t b0f[4][2], b1f[4][2];
            #pragma unroll
            for (int nf = 0; nf < 4; ++nf) {
                const int nr = (wn * 32 + nf * 8 + arow) * (LDP * 2);
                b0f[nf][0] = *(const uint32_t*)(bsm0 + nr + kbyte);
                b0f[nf][1] = *(const uint32_t*)(bsm0 + nr + kbyte + 16);
                b1f[nf][0] = *(const uint32_t*)(bsm1 + nr + kbyte);
                b1f[nf][1] = *(const uint32_t*)(bsm1 + nr + kbyte + 16);
            }

            uint32_t af[4][4];
            #pragma unroll
            for (int mf = 0; mf < 4; ++mf) {
                const int mr = (wm * 64 + mf * 16 + arow) * (LDP * 2);
                af[mf][0] = *(const uint32_t*)(asm0 + mr + kbyte);
                af[mf][1] = *(const uint32_t*)(asm0 + mr + 8 * (LDP * 2) + kbyte);
                af[mf][2] = *(const uint32_t*)(asm0 + mr + kbyte + 16);
                af[mf][3] = *(const uint32_t*)(asm0 + mr + 8 * (LDP * 2) + kbyte + 16);
            }
            #pragma unroll
            for (int mf = 0; mf < 4; ++mf)
                #pragma unroll
                for (int nf = 0; nf < 4; ++nf) {
                    hmma16816(acc[mf][nf][0], acc[mf][nf][1], acc[mf][nf][2], acc[mf][nf][3],
                              af[mf][0], af[mf][1], af[mf][2], af[mf][3],
                              b0f[nf][0], b0f[nf][1]);
                    hmma16816(acc[mf][nf][0], acc[mf][nf][1], acc[mf][nf][2], acc[mf][nf][3],
                              af[mf][0], af[mf][1], af[mf][2], af[mf][3],
                              b1f[nf][0], b1f[nf][1]);
                }

            #pragma unroll
            for (int mf = 0; mf < 4; ++mf) {
                const int mr = (wm * 64 + mf * 16 + arow) * (LDP * 2);
                af[mf][0] = *(const uint32_t*)(asm1 + mr + kbyte);
                af[mf][1] = *(const uint32_t*)(asm1 + mr + 8 * (LDP * 2) + kbyte);
                af[mf][2] = *(const uint32_t*)(asm1 + mr + kbyte + 16);
                af[mf][3] = *(const uint32_t*)(asm1 + mr + 8 * (LDP * 2) + kbyte + 16);
            }
            #pragma unroll
            for (int mf = 0; mf < 4; ++mf)
                #pragma unroll
                for (int nf = 0; nf < 4; ++nf)
                    hmma16816(acc[mf][nf][0], acc[mf][nf][1], acc[mf][nf][2], acc[mf][nf][3],
                              af[mf][0], af[mf][1], af[mf][2], af[mf][3],
                              b0f[nf][0], b0f[nf][1]);
        }
    }

    #pragma unroll
    for (int mf = 0; mf < 4; ++mf) {
        const int mrow = m0 + wm * 64 + mf * 16 + arow;
        #pragma unroll
        for (int nf = 0; nf < 4; ++nf) {
            const int ncol = n0 + wn * 32 + nf * 8 + (lane & 3) * 2;
            if (ncol < N) {
                float2 bv = bias ? *(const float2*)(bias + ncol)
                                 : make_float2(0.f, 0.f);
                const float v00 = acc[mf][nf][0] + bv.x;
                const float v01 = acc[mf][nf][1] + bv.y;
                const float v10 = acc[mf][nf][2] + bv.x;
                const float v11 = acc[mf][nf][3] + bv.y;
                if (C) {
                    *(float2*)(C + (size_t)mrow * ldc + ncol) = make_float2(v00, v01);
                    *(float2*)(C + (size_t)(mrow + 8) * ldc + ncol) = make_float2(v10, v11);
                }
                if (S0) {
                    __nv_bfloat162 h2, l2v;
                    h2.x = __float2bfloat16(v00); h2.y = __float2bfloat16(v01);
                    l2v.x = __float2bfloat16(v00 - __bfloat162float(h2.x));
                    l2v.y = __float2bfloat16(v01 - __bfloat162float(h2.y));
                    *(__nv_bfloat162*)(S0 + (size_t)mrow * kso + ncol) = h2;
                    *(__nv_bfloat162*)(S1 + (size_t)mrow * kso + ncol) = l2v;
                    h2.x = __float2bfloat16(v10); h2.y = __float2bfloat16(v11);
                    l2v.x = __float2bfloat16(v10 - __bfloat162float(h2.x));
                    l2v.y = __float2bfloat16(v11 - __bfloat162float(h2.y));
                    *(__nv_bfloat162*)(S0 + (size_t)(mrow + 8) * kso + ncol) = h2;
                    *(__nv_bfloat162*)(S1 + (size_t)(mrow + 8) * kso + ncol) = l2v;
                }
            }
        }
    }
}

// ---------------------------------------------------------------------------
// LSTM timestep (proven R10 fp32 FFMA2 version; epilogue now emits y as
// pre-split bf16 hi/lo for the next GEMM instead of fp32).
// ---------------------------------------------------------------------------
#define CK 64

__global__ __launch_bounds__(512, 1) void lstm_step(
    const float* __restrict__ pre, const float* __restrict__ Whh,
    const float* __restrict__ bhh,
    const float* __restrict__ hT_in, float* __restrict__ cT,
    float* __restrict__ hT_out,
    float* __restrict__ hfin, float* __restrict__ cfin,
    __nv_bfloat16* __restrict__ y0, __nv_bfloat16* __restrict__ y1, int ystr,
    int t, int d)
{
    extern __shared__ float sm[];
    float* hsm  = sm;
    float* wsm  = sm + (size_t)d * 32;
    float* psum = wsm + 4 * 2 * 32 * CK;

    const int tid = threadIdx.x;
    const int q   = tid >> 7;
    const int qt  = tid & 127;
    const int b   = qt & 31;
    const int r   = qt >> 5;
    const int j0  = blockIdx.x * 8;

    const int nch   = (d + CK - 1) / CK;
    const int iters = (nch + 3) >> 2;

    const int lrow = qt >> 2;
    const int lq   = (qt & 3) << 2;
    const float* wsrc = Whh + ((size_t)(lrow >> 3) * d + j0 + (lrow & 7)) * d;
    float* wq = wsm + q * (2 * 32 * CK);

    float4 pf[4];
    {
        const int c = q;
        if (c < nch) {
            const int kb = c * CK;
            const int ckc = (d - kb < CK) ? (d - kb) : CK;
            #pragma unroll
            for (int u = 0; u < 4; ++u) {
                const int col = lq + u * 16;
                pf[u] = (col < ckc) ? *(const float4*)(wsrc + kb + col)
                                    : make_float4(0.f, 0.f, 0.f, 0.f);
            }
        }
    }

    const int total = d * 32;
    for (int i = tid * 4; i < total; i += 2048)
        *(float4*)(hsm + i) = *(const float4*)(hT_in + i);

    unsigned long long acc2[2][4];
    #pragma unroll
    for (int jj = 0; jj < 2; ++jj)
        #pragma unroll
        for (int g = 0; g < 4; ++g) acc2[jj][g] = 0ull;

    int p = 0;
    for (int it = 0; it < iters; ++it) {
        const int c = q + it * 4;
        const bool has = (c < nch);
        float* wb = wq + p * (32 * CK);

        if (has) {
            #pragma unroll
            for (int u = 0; u < 4; ++u)
                *(float4*)(wb + lrow * CK + lq + u * 16) = pf[u];
        }
        __syncthreads();

        const int cn = c + 4;
        if (cn < nch) {
            const int kb = cn * CK;
            const int ckc = (d - kb < CK) ? (d - kb) : CK;
            #pragma unroll
            for (int u = 0; u < 4; ++u) {
                const int col = lq + u * 16;
                pf[u] = (col < ckc) ? *(const float4*)(wsrc + kb + col)
                                    : make_float4(0.f, 0.f, 0.f, 0.f);
            }
        }

        if (has) {
            const int kb = c * CK;
            const int ckc = (d - kb < CK) ? (d - kb) : CK;
            const float* hh = hsm + (size_t)kb * 32 + b;
            #pragma unroll 2
            for (int kk = 0; kk < ckc; kk += 4) {
                const float h0v = hh[(kk    ) * 32];
                const float h1v = hh[(kk + 1) * 32];
                const float h2v = hh[(kk + 2) * 32];
                const float h3v = hh[(kk + 3) * 32];
                const unsigned long long hp0 = pack2(h0v, h1v);
                const unsigned long long hp1 = pack2(h2v, h3v);
                #pragma unroll
                for (int g = 0; g < 4; ++g) {
                    F4U U; U.f = *(const float4*)(wb + (g * 8 + r) * CK + kk);
                    acc2[0][g] = ffma2(U.u[0], hp0, acc2[0][g]);
                    acc2[0][g] = ffma2(U.u[1], hp1, acc2[0][g]);
                    F4U V; V.f = *(const float4*)(wb + (g * 8 + r + 4) * CK + kk);
                    acc2[1][g] = ffma2(V.u[0], hp0, acc2[1][g]);
                    acc2[1][g] = ffma2(V.u[1], hp1, acc2[1][g]);
                }
            }
        }
        p ^= 1;
    }

    float a[2][4];
    #pragma unroll
    for (int jj = 0; jj < 2; ++jj)
        #pragma unroll
        for (int g = 0; g < 4; ++g) {
            float2 s = unpack2(acc2[jj][g]);
            a[jj][g] = s.x + s.y;
        }

    if (q != 0) {
        #pragma unroll
        for (int jj = 0; jj < 2; ++jj)
            *(float4*)(psum + (size_t)(((q - 1) * 8) + jj * 4 + r) * 128 + b * 4) =
                make_float4(a[jj][0], a[jj][1], a[jj][2], a[jj][3]);
    }
    __syncthreads();

    if (q == 0) {
        const float* pp = pre + (size_t)(b * Tt + t) * (4 * d);
        #pragma unroll
        for (int jj = 0; jj < 2; ++jj) {
            const int j = j0 + r + jj * 4;
            float s0 = a[jj][0], s1 = a[jj][1], s2 = a[jj][2], s3 = a[jj][3];
            #pragma unroll
            for (int qq = 0; qq < 3; ++qq) {
                float4 ps = *(const float4*)(psum + (size_t)(qq * 8 + jj * 4 + r) * 128 + b * 4);
                s0 += ps.x; s1 += ps.y; s2 += ps.z; s3 += ps.w;
            }
            const float gi = s0 + pp[            j] + bhh[            j];
            const float gf = s1 + pp[    d + j] + bhh[    d + j];
            const float gg = s2 + pp[2 * d + j] + bhh[2 * d + j];
            const float go = s3 + pp[3 * d + j] + bhh[3 * d + j];

            const float si = 1.f / (1.f + expf(-gi));
            const float sf = 1.f / (1.f + expf(-gf));
            const float so = 1.f / (1.f + expf(-go));
            const float cn = sf * cT[j * 32 + b] + si * tanhf(gg);
            const float hn = so * tanhf(cn);

            cT[j * 32 + b]     = cn;
            hT_out[j * 32 + b] = hn;
            const __nv_bfloat16 hhi = __float2bfloat16(hn);
            y0[(size_t)(b * Tt + t) * ystr + j] = hhi;
            y1[(size_t)(b * Tt + t) * ystr + j] =
                __float2bfloat16(hn - __bfloat162float(hhi));
            if (t == Tt - 1) {
                hfin[(size_t)b * d + j] = hn;
                cfin[(size_t)b * d + j] = cn;
            }
        }
    }
}

// ---- helpers ----
// generic fp32 [R][K0] -> bf16 hi/lo [R][KP] split with zero K-padding
__global__ void split_mat(const float* __restrict__ src,
                          __nv_bfloat16* __restrict__ d0,
                          __nv_bfloat16* __restrict__ d1, int R, int K0, int KP)
{
    size_t idx = (size_t)blockIdx.x * 256 + threadIdx.x;
    if (idx < (size_t)R * KP) {
        int k = (int)(idx % KP);
        int rr = (int)(idx / KP);
        float v = (k < K0) ? src[(size_t)rr * K0 + k] : 0.f;
        __nv_bfloat16 hi = __float2bfloat16(v);
        d0[idx] = hi;
        d1[idx] = __float2bfloat16(v - __bfloat162float(hi));
    }
}

// fused prep: WT split (transpose of define_W) + Wih0 split + layer-0 state
__global__ void prep_all(const float* __restrict__ dW,
                         __nv_bfloat16* __restrict__ WT0, __nv_bfloat16* __restrict__ WT1,
                         const float* __restrict__ Wih0,
                         __nv_bfloat16* __restrict__ WB0, __nv_bfloat16* __restrict__ WB1,
                         const float* __restrict__ h0, const float* __restrict__ c0,
                         float* __restrict__ hT, float* __restrict__ cT)
{
    size_t idx = (size_t)blockIdx.x * 256 + threadIdx.x;
    if (idx < (size_t)512 * EKP) {                  // WT split: [n=512][k=448]
        int n = (int)(idx / EKP), k = (int)(idx % EKP);
        float v = (k < Ee) ? dW[(size_t)k * Mm + n] : 0.f;
        __nv_bfloat16 hi = __float2bfloat16(v);
        WT0[idx] = hi;
        WT1[idx] = __float2bfloat16(v - __bfloat162float(hi));
    }
    if (idx < (size_t)4 * Hh * Mm) {                // Wih0 split (no pad)
        float v = Wih0[idx];
        __nv_bfloat16 hi = __float2bfloat16(v);
        WB0[idx] = hi;
        WB1[idx] = __float2bfloat16(v - __bfloat162float(hi));
    }
    if (idx < (size_t)Hh * 32) {                    // layer-0 state [d][32]
        int j = (int)(idx >> 5), b = (int)(idx & 31);
        hT[idx] = h0[(size_t)b * Hh + j];
        cT[idx] = c0[(size_t)b * Hh + j];
    }
}

__global__ void transpose_state(const float* __restrict__ h0, const float* __restrict__ c0,
                                float* __restrict__ hT, float* __restrict__ cT, int d)
{
    int idx = blockIdx.x * 256 + threadIdx.x;
    if (idx < d * 32) {
        int j = idx >> 5, b = idx & 31;
        hT[idx] = h0[(size_t)b * d + j];
        cT[idx] = c0[(size_t)b * d + j];
    }
}

// ---------------------------------------------------------------------------
extern "C" void kernel_launch(void* const* d_in, const int* in_sizes, int n_in,
                              void* d_out, int out_size)
{
    (void)in_sizes; (void)n_in; (void)out_size;

    const int*   ids  = (const int*)  d_in[0];
    const float* emb  = (const float*)d_in[1];
    const float* dW   = (const float*)d_in[2];
    const float* db   = (const float*)d_in[3];
    const float* Wih0 = (const float*)d_in[4];
    const float* Whh0 = (const float*)d_in[5];
    const float* bih0 = (const float*)d_in[6];
    const float* bhh0 = (const float*)d_in[7];
    const float* h00  = (const float*)d_in[8];
    const float* c00  = (const float*)d_in[9];
    const float* Wih1 = (const float*)d_in[10];
    const float* Whh1 = (const float*)d_in[11];
    const float* bih1 = (const float*)d_in[12];
    const float* bhh1 = (const float*)d_in[13];
    const float* h01  = (const float*)d_in[14];
    const float* c01  = (const float*)d_in[15];
    const float* Wih2 = (const float*)d_in[16];
    const float* Whh2 = (const float*)d_in[17];
    const float* bih2 = (const float*)d_in[18];
    const float* bhh2 = (const float*)d_in[19];
    const float* h02  = (const float*)d_in[20];
    const float* c02  = (const float*)d_in[21];
    float* out = (float*)d_out;

    float *PRE, *HT, *CT;
    __nv_bfloat16 *E0, *E1, *WT0, *WT1, *WB0, *WB1, *AB0, *AB1, *A0s, *A1s;
    cudaGetSymbolAddress((void**)&PRE, g_PRE);
    cudaGetSymbolAddress((void**)&HT,  g_HT);
    cudaGetSymbolAddress((void**)&CT,  g_CT);
    cudaGetSymbolAddress((void**)&E0,  g_E0);
    cudaGetSymbolAddress((void**)&E1,  g_E1);
    cudaGetSymbolAddress((void**)&WT0, g_WT0);
    cudaGetSymbolAddress((void**)&WT1, g_WT1);
    cudaGetSymbolAddress((void**)&WB0, g_WB0);
    cudaGetSymbolAddress((void**)&WB1, g_WB1);
    cudaGetSymbolAddress((void**)&AB0, g_AB0);
    cudaGetSymbolAddress((void**)&AB1, g_AB1);
    cudaGetSymbolAddress((void**)&A0s, g_A0);
    cudaGetSymbolAddress((void**)&A1s, g_A1);
    float* hTp[2] = { HT, HT + Hh * 32 };

    const size_t SM_H = (size_t)Hh * 32 * 4 + 4 * 2 * 32 * CK * 4 + 24 * 128 * 4;
    const size_t SM_E = (size_t)Ee * 32 * 4 + 4 * 2 * 32 * CK * 4 + 24 * 128 * 4;
    cudaFuncSetAttribute(lstm_step,
                         cudaFuncAttributeMaxDynamicSharedMemorySize, (int)SM_H);
    cudaFuncSetAttribute(gemm_hmma,
                         cudaFuncAttributeMaxDynamicSharedMemorySize, LG_SMEM);

    const size_t OFF_H0 = (size_t)Bb * Tt * Vv;
    const size_t OFF_C0 = OFF_H0 + (size_t)Bb * Hh;
    const size_t OFF_H1 = OFF_C0 + (size_t)Bb * Hh;
    const size_t OFF_C1 = OFF_H1 + (size_t)Bb * Hh;
    const size_t OFF_H2 = OFF_C1 + (size_t)Bb * Hh;
    const size_t OFF_C2 = OFF_H2 + (size_t)Bb * Ee;

    // #1 prep (WT+Wih0 splits, state0), #2 emb split,
    // #3 DeFINE HMMA (split-out), #4 layer-0 HMMA GEMM  <- ncu target
    prep_all<<<(int)(((size_t)4 * Hh * Mm + 255) / 256), 256>>>(
        dW, WT0, WT1, Wih0, WB0, WB1, h00, c00, hTp[0], CT);
    split_mat<<<(int)(((size_t)Vv * EKP + 255) / 256), 256>>>(
        emb, E0, E1, Vv, Ee, EKP);
    gemm_hmma<<<dim3(Mm / 128, NT / 128), 256, LG_SMEM>>>(
        E0, E1, WT0, WT1, nullptr, db, ids, AB0, AB1,
        Mm, EKP, 0, Mm);
    gemm_hmma<<<dim3(4 * Hh / 128, NT / 128), 256, LG_SMEM>>>(
        AB0, AB1, WB0, WB1, PRE, bih0, nullptr, nullptr, nullptr,
        4 * Hh, Mm, 4 * Hh, 0);

    // ================= layer 0 recurrence =================
    for (int t = 0; t < Tt; ++t) {
        int s = t & 1;
        lstm_step<<<Hh / 8, 512, SM_H>>>(PRE, Whh0, bhh0, hTp[s], CT, hTp[1 - s],
                                         out + OFF_H0, out + OFF_C0,
                                         AB0, AB1, Hh, t, Hh);
    }

    // ================= layer 1 =================
    split_mat<<<(int)(((size_t)4 * Hh * Hh + 255) / 256), 256>>>(
        Wih1, WB0, WB1, 4 * Hh, Hh, Hh);
    gemm_hmma<<<dim3(4 * Hh / 128, NT / 128), 256, LG_SMEM>>>(
        AB0, AB1, WB0, WB1, PRE, bih1, nullptr, nullptr, nullptr,
        4 * Hh, Hh, 4 * Hh, 0);
    transpose_state<<<(Hh * 32 + 255) / 256, 256>>>(h01, c01, hTp[0], CT, Hh);
    for (int t = 0; t < Tt; ++t) {
        int s = t & 1;
        lstm_step<<<Hh / 8, 512, SM_H>>>(PRE, Whh1, bhh1, hTp[s], CT, hTp[1 - s],
                                         out + OFF_H1, out + OFF_C1,
                                         AB0, AB1, Hh, t, Hh);
    }

    // ================= layer 2 =================
    split_mat<<<(int)(((size_t)4 * Ee * Hh + 255) / 256), 256>>>(
        Wih2, WB0, WB1, 4 * Ee, Hh, Hh);
    gemm_hmma<<<dim3((4 * Ee + 127) / 128, NT / 128), 256, LG_SMEM>>>(
        AB0, AB1, WB0, WB1, PRE, bih2, nullptr, nullptr, nullptr,
        4 * Ee, Hh, 4 * Ee, 0);
    transpose_state<<<(Ee * 32 + 255) / 256, 256>>>(h02, c02, hTp[0], CT, Ee);
    for (int t = 0; t < Tt; ++t) {
        int s = t & 1;
        lstm_step<<<Ee / 8, 512, SM_E>>>(PRE, Whh2, bhh2, hTp[s], CT, hTp[1 - s],
                                         out + OFF_H2, out + OFF_C2,
                                         A0s, A1s, EKP, t, Ee);
    }

    // ---- tied-embedding logits (A0s/A1s pad columns stay zero) ----
    gemm_hmma<<<dim3(Vv / 128, NT / 128), 256, LG_SMEM>>>(
        A0s, A1s, E0, E1, out, nullptr, nullptr, nullptr, nullptr,
        Vv, EKP, Vv, 0);
}

// round 16
// speedup vs baseline: 1.6054x; 1.6054x over previous
#include <cuda_runtime.h>
#include <cuda_bf16.h>
#include <cstdint>
#include <cstddef>

// ---------------------------------------------------------------------------
// AWD-LSTM forward: embed -> DeFINE -> 3x LSTM -> tied-embedding logits
// Shapes: B=32, T=128, V=32000, E=400, M=512, H=1152.
// Round 15: R14 structure kept (all parallel GEMMs on legacy HMMA, 3-term
// bf16 split, fp32 FFMA2 recurrence). ONE change: gemm_hmma staging is now
// cp.async double-buffered (chunk c+1 in flight while chunk c computes) —
// R14's ncu showed the unpipelined staging made every chunk eat a full L2
// round trip (issue=12%).
// ---------------------------------------------------------------------------

#define Bb 32
#define Tt 128
#define Vv 32000
#define Ee 400
#define Mm 512
#define Hh 1152
#define NT 4096           // B*T tokens
#define EKP 448           // emb K padded (400 -> 448)

// ---- scratch (device globals; no allocation allowed) ----
__device__ float g_PRE[NT * 4608];                  // gate preacts (has bih)
__device__ float g_HT [2][Hh * 32];                 // h ping-pong [d][32] fp32
__device__ float g_CT [Hh * 32];                    // c [d][32] fp32
__device__ __nv_bfloat16 g_E0[(size_t)Vv * EKP];    // emb hi
__device__ __nv_bfloat16 g_E1[(size_t)Vv * EKP];    // emb lo
__device__ __nv_bfloat16 g_WT0[512 * EKP];          // define_W^T hi
__device__ __nv_bfloat16 g_WT1[512 * EKP];          // define_W^T lo
__device__ __nv_bfloat16 g_WB0[(size_t)4608 * Hh];  // Wih splits (per layer)
__device__ __nv_bfloat16 g_WB1[(size_t)4608 * Hh];
__device__ __nv_bfloat16 g_AB0[(size_t)NT * Hh];    // activation splits
__device__ __nv_bfloat16 g_AB1[(size_t)NT * Hh];
__device__ __nv_bfloat16 g_A0[(size_t)NT * EKP];    // Y2 split (pad stays 0)
__device__ __nv_bfloat16 g_A1[(size_t)NT * EKP];

// ---- packed fp32 helpers ----
__device__ __forceinline__ unsigned long long ffma2(
    unsigned long long a, unsigned long long b, unsigned long long c)
{
    unsigned long long d;
    asm("fma.rn.f32x2 %0, %1, %2, %3;" : "=l"(d) : "l"(a), "l"(b), "l"(c));
    return d;
}
__device__ __forceinline__ unsigned long long pack2(float lo, float hi)
{
    unsigned long long r;
    asm("mov.b64 %0, {%1, %2};" : "=l"(r) : "f"(lo), "f"(hi));
    return r;
}
__device__ __forceinline__ float2 unpack2(unsigned long long v)
{
    float lo, hi;
    asm("mov.b64 {%0, %1}, %2;" : "=f"(lo), "=f"(hi) : "l"(v));
    return make_float2(lo, hi);
}
union F4U { float4 f; unsigned long long u[2]; };

__device__ __forceinline__ void hmma16816(
    float& c0, float& c1, float& c2, float& c3,
    uint32_t a0, uint32_t a1, uint32_t a2, uint32_t a3,
    uint32_t b0, uint32_t b1)
{
    asm volatile(
        "mma.sync.aligned.m16n8k16.row.col.f32.bf16.bf16.f32 "
        "{%0,%1,%2,%3}, {%4,%5,%6,%7}, {%8,%9}, {%0,%1,%2,%3};"
        : "+f"(c0), "+f"(c1), "+f"(c2), "+f"(c3)
        : "r"(a0), "r"(a1), "r"(a2), "r"(a3), "r"(b0), "r"(b1));
}

__device__ __forceinline__ uint32_t smem_u32(const void* p)
{
    uint32_t a;
    asm("{ .reg .u64 t; cvta.to.shared.u64 t, %1; cvt.u32.u64 %0, t; }"
        : "=r"(a) : "l"(p));
    return a;
}
__device__ __forceinline__ void cp16(uint32_t s, const void* g)
{
    asm volatile(
        "{ .reg .u64 gg; cvta.to.global.u64 gg, %1;"
        "  cp.async.cg.shared.global [%0], [gg], 16; }"
        :: "r"(s), "l"(g) : "memory");
}
#define CP_COMMIT() asm volatile("cp.async.commit_group;" ::: "memory")
#define CP_WAIT1()  asm volatile("cp.async.wait_group 1;" ::: "memory")
#define CP_WAIT0()  asm volatile("cp.async.wait_group 0;" ::: "memory")

// ---------------------------------------------------------------------------
// Generic HMMA GEMM-NT:  C[M,N] = A[M,Kp] @ B[N,Kp]^T + bias[N]
// A,B pre-split bf16 (hi/lo); 3-term product a0b0 + a0b1 + a1b0.
// CTA 128x128, 8 warps (64x32 warp tile), K chunks of 32, smem rows padded
// to 40 bf16 (conflict-free fragment loads). cp.async double-buffered
// staging. Optional ids gather, N tail, bias, bf16-split output.
// ---------------------------------------------------------------------------
#define LDP 40
#define LG_TILE (128 * LDP * 2)        // 10240 B per matrix tile
#define LG_BUF  (4 * LG_TILE)          // 40960 B per stage
#define LG_SMEM (2 * LG_BUF)           // 81920 B (double buffer)

__global__ __launch_bounds__(256, 2) void gemm_hmma(
    const __nv_bfloat16* __restrict__ A0, const __nv_bfloat16* __restrict__ A1,
    const __nv_bfloat16* __restrict__ B0, const __nv_bfloat16* __restrict__ B1,
    float* __restrict__ C, const float* __restrict__ bias,
    const int* __restrict__ ids,
    __nv_bfloat16* __restrict__ S0, __nv_bfloat16* __restrict__ S1,
    int N, int Kp, size_t ldc, int kso)
{
    extern __shared__ char smc[];
    const uint32_t sb = smem_u32(smc);

    const int tid  = threadIdx.x;
    const int wid  = tid >> 5;
    const int lane = tid & 31;
    const int wm   = wid & 1;
    const int wn   = wid >> 1;

    const int n0 = blockIdx.x * 128;
    const int m0 = blockIdx.y * 128;

    // staging: 64 threads per matrix, 2 rows per thread
    const int mtx = tid >> 6;
    const int rp  = tid & 63;
    const __nv_bfloat16 *s0, *s1;
    if (mtx < 2) {
        const int mr0 = m0 + 2 * rp, mr1 = m0 + 2 * rp + 1;
        const int ar0 = ids ? ids[mr0] : mr0;
        const int ar1 = ids ? ids[mr1] : mr1;
        const __nv_bfloat16* base = (mtx == 0) ? A0 : A1;
        s0 = base + (size_t)ar0 * Kp;
        s1 = base + (size_t)ar1 * Kp;
    } else {
        const int nr0 = n0 + 2 * rp, nr1 = n0 + 2 * rp + 1;
        const __nv_bfloat16* base = (mtx == 2) ? B0 : B1;
        s0 = base + (size_t)(nr0 < N ? nr0 : 0) * Kp;
        s1 = base + (size_t)(nr1 < N ? nr1 : 0) * Kp;
    }
    const uint32_t sd0 = sb + mtx * LG_TILE + (2 * rp    ) * (LDP * 2);
    const uint32_t sd1 = sb + mtx * LG_TILE + (2 * rp + 1) * (LDP * 2);

    float acc[4][4][4];
    #pragma unroll
    for (int i = 0; i < 4; ++i)
        #pragma unroll
        for (int j = 0; j < 4; ++j)
            #pragma unroll
            for (int k = 0; k < 4; ++k) acc[i][j][k] = 0.f;

    const int arow = (lane >> 2);
    const int akof = (lane & 3) * 2;
    const int nchunk = Kp >> 5;

    // issue chunk 0 into buffer 0
    {
        const char* p0 = (const char*)s0;
        const char* p1 = (const char*)s1;
        #pragma unroll
        for (int i = 0; i < 4; ++i) {
            cp16(sd0 + i * 16, p0 + i * 16);
            cp16(sd1 + i * 16, p1 + i * 16);
        }
        CP_COMMIT();
    }

    for (int c = 0; c < nchunk; ++c) {
        // issue chunk c+1 into the other buffer, then wait for chunk c
        if (c + 1 < nchunk) {
            const uint32_t bo = ((c + 1) & 1) * LG_BUF;
            const char* p0 = (const char*)(s0 + (c + 1) * 32);
            const char* p1 = (const char*)(s1 + (c + 1) * 32);
            #pragma unroll
            for (int i = 0; i < 4; ++i) {
                cp16(sd0 + bo + i * 16, p0 + i * 16);
                cp16(sd1 + bo + i * 16, p1 + i * 16);
            }
            CP_COMMIT();
            CP_WAIT1();
        } else {
            CP_WAIT0();
        }
        __syncthreads();   // chunk c staged by ALL threads

        const char* cb   = smc + (c & 1) * LG_BUF;
        const char* asm0 = cb;
        const char* asm1 = cb + LG_TILE;
        const char* bsm0 = cb + 2 * LG_TILE;
        const char* bsm1 = cb + 3 * LG_TILE;

        #pragma unroll
        for (int ks = 0; ks < 2; ++ks) {
            const int kbyte = (ks * 16 + akof) * 2;

            uint32_t b0f[4][2], b1f[4][2];
            #pragma unroll
            for (int nf = 0; nf < 4; ++nf) {
                const int nr = (wn * 32 + nf * 8 + arow) * (LDP * 2);
                b0f[nf][0] = *(const uint32_t*)(bsm0 + nr + kbyte);
                b0f[nf][1] = *(const uint32_t*)(bsm0 + nr + kbyte + 16);
                b1f[nf][0] = *(const uint32_t*)(bsm1 + nr + kbyte);
                b1f[nf][1] = *(const uint32_t*)(bsm1 + nr + kbyte + 16);
            }

            uint32_t af[4][4];
            #pragma unroll
            for (int mf = 0; mf < 4; ++mf) {
                const int mr = (wm * 64 + mf * 16 + arow) * (LDP * 2);
                af[mf][0] = *(const uint32_t*)(asm0 + mr + kbyte);
                af[mf][1] = *(const uint32_t*)(asm0 + mr + 8 * (LDP * 2) + kbyte);
                af[mf][2] = *(const uint32_t*)(asm0 + mr + kbyte + 16);
                af[mf][3] = *(const uint32_t*)(asm0 + mr + 8 * (LDP * 2) + kbyte + 16);
            }
            #pragma unroll
            for (int mf = 0; mf < 4; ++mf)
                #pragma unroll
                for (int nf = 0; nf < 4; ++nf) {
                    hmma16816(acc[mf][nf][0], acc[mf][nf][1], acc[mf][nf][2], acc[mf][nf][3],
                              af[mf][0], af[mf][1], af[mf][2], af[mf][3],
                              b0f[nf][0], b0f[nf][1]);
                    hmma16816(acc[mf][nf][0], acc[mf][nf][1], acc[mf][nf][2], acc[mf][nf][3],
                              af[mf][0], af[mf][1], af[mf][2], af[mf][3],
                              b1f[nf][0], b1f[nf][1]);
                }

            #pragma unroll
            for (int mf = 0; mf < 4; ++mf) {
                const int mr = (wm * 64 + mf * 16 + arow) * (LDP * 2);
                af[mf][0] = *(const uint32_t*)(asm1 + mr + kbyte);
                af[mf][1] = *(const uint32_t*)(asm1 + mr + 8 * (LDP * 2) + kbyte);
                af[mf][2] = *(const uint32_t*)(asm1 + mr + kbyte + 16);
                af[mf][3] = *(const uint32_t*)(asm1 + mr + 8 * (LDP * 2) + kbyte + 16);
            }
            #pragma unroll
            for (int mf = 0; mf < 4; ++mf)
                #pragma unroll
                for (int nf = 0; nf < 4; ++nf)
                    hmma16816(acc[mf][nf][0], acc[mf][nf][1], acc[mf][nf][2], acc[mf][nf][3],
                              af[mf][0], af[mf][1], af[mf][2], af[mf][3],
                              b0f[nf][0], b0f[nf][1]);
        }
        __syncthreads();   // done reading buf (c&1) before it is re-filled
    }

    #pragma unroll
    for (int mf = 0; mf < 4; ++mf) {
        const int mrow = m0 + wm * 64 + mf * 16 + arow;
        #pragma unroll
        for (int nf = 0; nf < 4; ++nf) {
            const int ncol = n0 + wn * 32 + nf * 8 + (lane & 3) * 2;
            if (ncol < N) {
                float2 bv = bias ? *(const float2*)(bias + ncol)
                                 : make_float2(0.f, 0.f);
                const float v00 = acc[mf][nf][0] + bv.x;
                const float v01 = acc[mf][nf][1] + bv.y;
                const float v10 = acc[mf][nf][2] + bv.x;
                const float v11 = acc[mf][nf][3] + bv.y;
                if (C) {
                    *(float2*)(C + (size_t)mrow * ldc + ncol) = make_float2(v00, v01);
                    *(float2*)(C + (size_t)(mrow + 8) * ldc + ncol) = make_float2(v10, v11);
                }
                if (S0) {
                    __nv_bfloat162 h2, l2v;
                    h2.x = __float2bfloat16(v00); h2.y = __float2bfloat16(v01);
                    l2v.x = __float2bfloat16(v00 - __bfloat162float(h2.x));
                    l2v.y = __float2bfloat16(v01 - __bfloat162float(h2.y));
                    *(__nv_bfloat162*)(S0 + (size_t)mrow * kso + ncol) = h2;
                    *(__nv_bfloat162*)(S1 + (size_t)mrow * kso + ncol) = l2v;
                    h2.x = __float2bfloat16(v10); h2.y = __float2bfloat16(v11);
                    l2v.x = __float2bfloat16(v10 - __bfloat162float(h2.x));
                    l2v.y = __float2bfloat16(v11 - __bfloat162float(h2.y));
                    *(__nv_bfloat162*)(S0 + (size_t)(mrow + 8) * kso + ncol) = h2;
                    *(__nv_bfloat162*)(S1 + (size_t)(mrow + 8) * kso + ncol) = l2v;
                }
            }
        }
    }
}

// ---------------------------------------------------------------------------
// LSTM timestep (proven R10 fp32 FFMA2 version; epilogue emits y pre-split)
// ---------------------------------------------------------------------------
#define CK 64

__global__ __launch_bounds__(512, 1) void lstm_step(
    const float* __restrict__ pre, const float* __restrict__ Whh,
    const float* __restrict__ bhh,
    const float* __restrict__ hT_in, float* __restrict__ cT,
    float* __restrict__ hT_out,
    float* __restrict__ hfin, float* __restrict__ cfin,
    __nv_bfloat16* __restrict__ y0, __nv_bfloat16* __restrict__ y1, int ystr,
    int t, int d)
{
    extern __shared__ float sm[];
    float* hsm  = sm;
    float* wsm  = sm + (size_t)d * 32;
    float* psum = wsm + 4 * 2 * 32 * CK;

    const int tid = threadIdx.x;
    const int q   = tid >> 7;
    const int qt  = tid & 127;
    const int b   = qt & 31;
    const int r   = qt >> 5;
    const int j0  = blockIdx.x * 8;

    const int nch   = (d + CK - 1) / CK;
    const int iters = (nch + 3) >> 2;

    const int lrow = qt >> 2;
    const int lq   = (qt & 3) << 2;
    const float* wsrc = Whh + ((size_t)(lrow >> 3) * d + j0 + (lrow & 7)) * d;
    float* wq = wsm + q * (2 * 32 * CK);

    float4 pf[4];
    {
        const int c = q;
        if (c < nch) {
            const int kb = c * CK;
            const int ckc = (d - kb < CK) ? (d - kb) : CK;
            #pragma unroll
            for (int u = 0; u < 4; ++u) {
                const int col = lq + u * 16;
                pf[u] = (col < ckc) ? *(const float4*)(wsrc + kb + col)
                                    : make_float4(0.f, 0.f, 0.f, 0.f);
            }
        }
    }

    const int total = d * 32;
    for (int i = tid * 4; i < total; i += 2048)
        *(float4*)(hsm + i) = *(const float4*)(hT_in + i);

    unsigned long long acc2[2][4];
    #pragma unroll
    for (int jj = 0; jj < 2; ++jj)
        #pragma unroll
        for (int g = 0; g < 4; ++g) acc2[jj][g] = 0ull;

    int p = 0;
    for (int it = 0; it < iters; ++it) {
        const int c = q + it * 4;
        const bool has = (c < nch);
        float* wb = wq + p * (32 * CK);

        if (has) {
            #pragma unroll
            for (int u = 0; u < 4; ++u)
                *(float4*)(wb + lrow * CK + lq + u * 16) = pf[u];
        }
        __syncthreads();

        const int cn = c + 4;
        if (cn < nch) {
            const int kb = cn * CK;
            const int ckc = (d - kb < CK) ? (d - kb) : CK;
            #pragma unroll
            for (int u = 0; u < 4; ++u) {
                const int col = lq + u * 16;
                pf[u] = (col < ckc) ? *(const float4*)(wsrc + kb + col)
                                    : make_float4(0.f, 0.f, 0.f, 0.f);
            }
        }

        if (has) {
            const int kb = c * CK;
            const int ckc = (d - kb < CK) ? (d - kb) : CK;
            const float* hh = hsm + (size_t)kb * 32 + b;
            #pragma unroll 2
            for (int kk = 0; kk < ckc; kk += 4) {
                const float h0v = hh[(kk    ) * 32];
                const float h1v = hh[(kk + 1) * 32];
                const float h2v = hh[(kk + 2) * 32];
                const float h3v = hh[(kk + 3) * 32];
                const unsigned long long hp0 = pack2(h0v, h1v);
                const unsigned long long hp1 = pack2(h2v, h3v);
                #pragma unroll
                for (int g = 0; g < 4; ++g) {
                    F4U U; U.f = *(const float4*)(wb + (g * 8 + r) * CK + kk);
                    acc2[0][g] = ffma2(U.u[0], hp0, acc2[0][g]);
                    acc2[0][g] = ffma2(U.u[1], hp1, acc2[0][g]);
                    F4U V; V.f = *(const float4*)(wb + (g * 8 + r + 4) * CK + kk);
                    acc2[1][g] = ffma2(V.u[0], hp0, acc2[1][g]);
                    acc2[1][g] = ffma2(V.u[1], hp1, acc2[1][g]);
                }
            }
        }
        p ^= 1;
    }

    float a[2][4];
    #pragma unroll
    for (int jj = 0; jj < 2; ++jj)
        #pragma unroll
        for (int g = 0; g < 4; ++g) {
            float2 s = unpack2(acc2[jj][g]);
            a[jj][g] = s.x + s.y;
        }

    if (q != 0) {
        #pragma unroll
        for (int jj = 0; jj < 2; ++jj)
            *(float4*)(psum + (size_t)(((q - 1) * 8) + jj * 4 + r) * 128 + b * 4) =
                make_float4(a[jj][0], a[jj][1], a[jj][2], a[jj][3]);
    }
    __syncthreads();

    if (q == 0) {
        const float* pp = pre + (size_t)(b * Tt + t) * (4 * d);
        #pragma unroll
        for (int jj = 0; jj < 2; ++jj) {
            const int j = j0 + r + jj * 4;
            float s0 = a[jj][0], s1 = a[jj][1], s2 = a[jj][2], s3 = a[jj][3];
            #pragma unroll
            for (int qq = 0; qq < 3; ++qq) {
                float4 ps = *(const float4*)(psum + (size_t)(qq * 8 + jj * 4 + r) * 128 + b * 4);
                s0 += ps.x; s1 += ps.y; s2 += ps.z; s3 += ps.w;
            }
            const float gi = s0 + pp[            j] + bhh[            j];
            const float gf = s1 + pp[    d + j] + bhh[    d + j];
            const float gg = s2 + pp[2 * d + j] + bhh[2 * d + j];
            const float go = s3 + pp[3 * d + j] + bhh[3 * d + j];

            const float si = 1.f / (1.f + expf(-gi));
            const float sf = 1.f / (1.f + expf(-gf));
            const float so = 1.f / (1.f + expf(-go));
            const float cn = sf * cT[j * 32 + b] + si * tanhf(gg);
            const float hn = so * tanhf(cn);

            cT[j * 32 + b]     = cn;
            hT_out[j * 32 + b] = hn;
            const __nv_bfloat16 hhi = __float2bfloat16(hn);
            y0[(size_t)(b * Tt + t) * ystr + j] = hhi;
            y1[(size_t)(b * Tt + t) * ystr + j] =
                __float2bfloat16(hn - __bfloat162float(hhi));
            if (t == Tt - 1) {
                hfin[(size_t)b * d + j] = hn;
                cfin[(size_t)b * d + j] = cn;
            }
        }
    }
}

// ---- helpers ----
__global__ void split_mat(const float* __restrict__ src,
                          __nv_bfloat16* __restrict__ d0,
                          __nv_bfloat16* __restrict__ d1, int R, int K0, int KP)
{
    size_t idx = (size_t)blockIdx.x * 256 + threadIdx.x;
    if (idx < (size_t)R * KP) {
        int k = (int)(idx % KP);
        int rr = (int)(idx / KP);
        float v = (k < K0) ? src[(size_t)rr * K0 + k] : 0.f;
        __nv_bfloat16 hi = __float2bfloat16(v);
        d0[idx] = hi;
        d1[idx] = __float2bfloat16(v - __bfloat162float(hi));
    }
}

__global__ void prep_all(const float* __restrict__ dW,
                         __nv_bfloat16* __restrict__ WT0, __nv_bfloat16* __restrict__ WT1,
                         const float* __restrict__ Wih0,
                         __nv_bfloat16* __restrict__ WB0, __nv_bfloat16* __restrict__ WB1,
                         const float* __restrict__ h0, const float* __restrict__ c0,
                         float* __restrict__ hT, float* __restrict__ cT)
{
    size_t idx = (size_t)blockIdx.x * 256 + threadIdx.x;
    if (idx < (size_t)512 * EKP) {
        int n = (int)(idx / EKP), k = (int)(idx % EKP);
        float v = (k < Ee) ? dW[(size_t)k * Mm + n] : 0.f;
        __nv_bfloat16 hi = __float2bfloat16(v);
        WT0[idx] = hi;
        WT1[idx] = __float2bfloat16(v - __bfloat162float(hi));
    }
    if (idx < (size_t)4 * Hh * Mm) {
        float v = Wih0[idx];
        __nv_bfloat16 hi = __float2bfloat16(v);
        WB0[idx] = hi;
        WB1[idx] = __float2bfloat16(v - __bfloat162float(hi));
    }
    if (idx < (size_t)Hh * 32) {
        int j = (int)(idx >> 5), b = (int)(idx & 31);
        hT[idx] = h0[(size_t)b * Hh + j];
        cT[idx] = c0[(size_t)b * Hh + j];
    }
}

__global__ void transpose_state(const float* __restrict__ h0, const float* __restrict__ c0,
                                float* __restrict__ hT, float* __restrict__ cT, int d)
{
    int idx = blockIdx.x * 256 + threadIdx.x;
    if (idx < d * 32) {
        int j = idx >> 5, b = idx & 31;
        hT[idx] = h0[(size_t)b * d + j];
        cT[idx] = c0[(size_t)b * d + j];
    }
}

// ---------------------------------------------------------------------------
extern "C" void kernel_launch(void* const* d_in, const int* in_sizes, int n_in,
                              void* d_out, int out_size)
{
    (void)in_sizes; (void)n_in; (void)out_size;

    const int*   ids  = (const int*)  d_in[0];
    const float* emb  = (const float*)d_in[1];
    const float* dW   = (const float*)d_in[2];
    const float* db   = (const float*)d_in[3];
    const float* Wih0 = (const float*)d_in[4];
    const float* Whh0 = (const float*)d_in[5];
    const float* bih0 = (const float*)d_in[6];
    const float* bhh0 = (const float*)d_in[7];
    const float* h00  = (const float*)d_in[8];
    const float* c00  = (const float*)d_in[9];
    const float* Wih1 = (const float*)d_in[10];
    const float* Whh1 = (const float*)d_in[11];
    const float* bih1 = (const float*)d_in[12];
    const float* bhh1 = (const float*)d_in[13];
    const float* h01  = (const float*)d_in[14];
    const float* c01  = (const float*)d_in[15];
    const float* Wih2 = (const float*)d_in[16];
    const float* Whh2 = (const float*)d_in[17];
    const float* bih2 = (const float*)d_in[18];
    const float* bhh2 = (const float*)d_in[19];
    const float* h02  = (const float*)d_in[20];
    const float* c02  = (const float*)d_in[21];
    float* out = (float*)d_out;

    float *PRE, *HT, *CT;
    __nv_bfloat16 *E0, *E1, *WT0, *WT1, *WB0, *WB1, *AB0, *AB1, *A0s, *A1s;
    cudaGetSymbolAddress((void**)&PRE, g_PRE);
    cudaGetSymbolAddress((void**)&HT,  g_HT);
    cudaGetSymbolAddress((void**)&CT,  g_CT);
    cudaGetSymbolAddress((void**)&E0,  g_E0);
    cudaGetSymbolAddress((void**)&E1,  g_E1);
    cudaGetSymbolAddress((void**)&WT0, g_WT0);
    cudaGetSymbolAddress((void**)&WT1, g_WT1);
    cudaGetSymbolAddress((void**)&WB0, g_WB0);
    cudaGetSymbolAddress((void**)&WB1, g_WB1);
    cudaGetSymbolAddress((void**)&AB0, g_AB0);
    cudaGetSymbolAddress((void**)&AB1, g_AB1);
    cudaGetSymbolAddress((void**)&A0s, g_A0);
    cudaGetSymbolAddress((void**)&A1s, g_A1);
    float* hTp[2] = { HT, HT + Hh * 32 };

    const size_t SM_H = (size_t)Hh * 32 * 4 + 4 * 2 * 32 * CK * 4 + 24 * 128 * 4;
    const size_t SM_E = (size_t)Ee * 32 * 4 + 4 * 2 * 32 * CK * 4 + 24 * 128 * 4;
    cudaFuncSetAttribute(lstm_step,
                         cudaFuncAttributeMaxDynamicSharedMemorySize, (int)SM_H);
    cudaFuncSetAttribute(gemm_hmma,
                         cudaFuncAttributeMaxDynamicSharedMemorySize, LG_SMEM);

    const size_t OFF_H0 = (size_t)Bb * Tt * Vv;
    const size_t OFF_C0 = OFF_H0 + (size_t)Bb * Hh;
    const size_t OFF_H1 = OFF_C0 + (size_t)Bb * Hh;
    const size_t OFF_C1 = OFF_H1 + (size_t)Bb * Hh;
    const size_t OFF_H2 = OFF_C1 + (size_t)Bb * Hh;
    const size_t OFF_C2 = OFF_H2 + (size_t)Bb * Ee;

    // #1 prep (WT+Wih0 splits, state0), #2 emb split,
    // #3 DeFINE HMMA (split-out), #4 layer-0 HMMA GEMM  <- ncu target
    prep_all<<<(int)(((size_t)4 * Hh * Mm + 255) / 256), 256>>>(
        dW, WT0, WT1, Wih0, WB0, WB1, h00, c00, hTp[0], CT);
    split_mat<<<(int)(((size_t)Vv * EKP + 255) / 256), 256>>>(
        emb, E0, E1, Vv, Ee, EKP);
    gemm_hmma<<<dim3(Mm / 128, NT / 128), 256, LG_SMEM>>>(
        E0, E1, WT0, WT1, nullptr, db, ids, AB0, AB1,
        Mm, EKP, 0, Mm);
    gemm_hmma<<<dim3(4 * Hh / 128, NT / 128), 256, LG_SMEM>>>(
        AB0, AB1, WB0, WB1, PRE, bih0, nullptr, nullptr, nullptr,
        4 * Hh, Mm, 4 * Hh, 0);

    // ================= layer 0 recurrence =================
    for (int t = 0; t < Tt; ++t) {
        int s = t & 1;
        lstm_step<<<Hh / 8, 512, SM_H>>>(PRE, Whh0, bhh0, hTp[s], CT, hTp[1 - s],
                                         out + OFF_H0, out + OFF_C0,
                                         AB0, AB1, Hh, t, Hh);
    }

    // ================= layer 1 =================
    split_mat<<<(int)(((size_t)4 * Hh * Hh + 255) / 256), 256>>>(
        Wih1, WB0, WB1, 4 * Hh, Hh, Hh);
    gemm_hmma<<<dim3(4 * Hh / 128, NT / 128), 256, LG_SMEM>>>(
        AB0, AB1, WB0, WB1, PRE, bih1, nullptr, nullptr, nullptr,
        4 * Hh, Hh, 4 * Hh, 0);
    transpose_state<<<(Hh * 32 + 255) / 256, 256>>>(h01, c01, hTp[0], CT, Hh);
    for (int t = 0; t < Tt; ++t) {
        int s = t & 1;
        lstm_step<<<Hh / 8, 512, SM_H>>>(PRE, Whh1, bhh1, hTp[s], CT, hTp[1 - s],
                                         out + OFF_H1, out + OFF_C1,
                                         AB0, AB1, Hh, t, Hh);
    }

    // ================= layer 2 =================
    split_mat<<<(int)(((size_t)4 * Ee * Hh + 255) / 256), 256>>>(
        Wih2, WB0, WB1, 4 * Ee, Hh, Hh);
    gemm_hmma<<<dim3((4 * Ee + 127) / 128, NT / 128), 256, LG_SMEM>>>(
        AB0, AB1, WB0, WB1, PRE, bih2, nullptr, nullptr, nullptr,
        4 * Ee, Hh, 4 * Ee, 0);
    transpose_state<<<(Ee * 32 + 255) / 256, 256>>>(h02, c02, hTp[0], CT, Ee);
    for (int t = 0; t < Tt; ++t) {
        int s = t & 1;
        lstm_step<<<Ee / 8, 512, SM_E>>>(PRE, Whh2, bhh2, hTp[s], CT, hTp[1 - s],
                                         out + OFF_H2, out + OFF_C2,
                                         A0s, A1s, EKP, t, Ee);
    }

    // ---- tied-embedding logits (A0s/A1s pad columns stay zero) ----
    gemm_hmma<<<dim3(Vv / 128, NT / 128), 256, LG_SMEM>>>(
        A0s, A1s, E0, E1, out, nullptr, nullptr, nullptr, nullptr,
        Vv, EKP, Vv, 0);
}